// round 12
// baseline (speedup 1.0000x reference)
#include <cuda_runtime.h>
#include <cstdint>
#include <cstddef>

// Fused axial attention on a 7x7 grid (N=512, Cq=64, Cv=512), ONE kernel.
// out[n,c,h,w] = sum_j p[n,h,w,j]   * vH[(n*7+w), c, j]
//             + sum_y p[n,h,w,7+y] * vW[(n*7+h), c, y]
// p = softmax over 14 of [eH (diag-masked, transposed), eW].
//
// Block = n. cp.async streams: group0 = q/k (50KB), then v chunks of 64
// channels (vH+vW, 25KB) double-buffered. Chunks 0,1 are issued BEFORE the
// logits compute, so the whole q/k+softmax phase hides under the v stream.

#define NEGV (-1e20f)

static __device__ __forceinline__ uint32_t s2u(const void* p) {
    return (uint32_t)__cvta_generic_to_shared(p);
}
#define CP_ASYNC16(dst_u32, src_ptr) \
    asm volatile("cp.async.cg.shared.global [%0], [%1], 16;" \
                 :: "r"(dst_u32), "l"(src_ptr))
#define CP_COMMIT()  asm volatile("cp.async.commit_group;")
#define CP_WAIT0()   asm volatile("cp.async.wait_group 0;")
#define CP_WAIT1()   asm volatile("cp.async.wait_group 1;")
#define CP_WAIT2()   asm volatile("cp.async.wait_group 2;")

// ---- shared layout (floats) ----
#define SL      452                 // qk slice stride (==4 mod 32)
#define TSL     (7 * SL)            // 3164 per tensor
#define LG_OFF  0                   // 686 (+2 pad)
#define PH_OFF  688                 // 49*8
#define PW_OFF  1080                // 49*8
#define QK_OFF  1472                // 4*3164 = 12656 (dead after logits)
#define BN_OFF  1472                // bounce aliases qk: 49*65 = 3185
#define CPADB   65
#define VB_OFF  14128               // 4 slots (2 chunks x {H,W}) * 3136
#define VSLOT   3136
#define SMEM_FLOATS 26672           // 106688 B -> 2 blocks/SM
#define SMEM_BYTES (SMEM_FLOATS * 4)

#define NTHR 448                    // 7 h-groups x 64 channels

static __device__ __forceinline__ void issue_chunk(
    const float* __restrict__ vH, const float* __restrict__ vW,
    uint32_t smb, int n, int ch, int Cv, size_t bstr, int tid)
{
    const int cmax7 = (Cv - ch * 64 >= 64 ? 64 : Cv - ch * 64) * 7;
    const float* bh = vH + (size_t)n * 7 * bstr + (size_t)(ch * 64) * 7;
    const float* bw = vW + (size_t)n * 7 * bstr + (size_t)(ch * 64) * 7;
    const int slot = (ch & 1) * 2;
    #pragma unroll
    for (int i = tid; i < 784; i += NTHR) {
        int w = i / 112, r = i - w * 112;
        if (r * 4 + 4 <= cmax7) {
            CP_ASYNC16(smb + (VB_OFF + (slot + 0) * VSLOT + w * 448) * 4 + r * 16,
                       bh + (size_t)w * bstr + r * 4);
            CP_ASYNC16(smb + (VB_OFF + (slot + 1) * VSLOT + w * 448) * 4 + r * 16,
                       bw + (size_t)w * bstr + r * 4);
        }
    }
    CP_COMMIT();
}

__global__ __launch_bounds__(NTHR, 2) void axattn_one(
    const float* __restrict__ qH, const float* __restrict__ kH,
    const float* __restrict__ vH,
    const float* __restrict__ qW, const float* __restrict__ kW,
    const float* __restrict__ vW,
    float* __restrict__ out, int Cv)
{
    extern __shared__ float sm[];
    const int n   = blockIdx.x;
    const int tid = threadIdx.x;
    const int c   = tid & 63;        // channel within chunk
    const int h   = tid >> 6;        // 0..6 (constant per warp-pair)
    const uint32_t smb = s2u(sm);
    const size_t bstr = (size_t)Cv * 7;
    const int nch = (Cv + 63) >> 6;

    // ---- group 0: q/k for both passes (straight float4 copies) ----
    {
        const float* t0 = qH + (size_t)n * 3136;
        const float* t1 = kH + (size_t)n * 3136;
        const float* t2 = qW + (size_t)n * 3136;
        const float* t3 = kW + (size_t)n * 3136;
        #pragma unroll
        for (int i = tid; i < 784; i += NTHR) {
            int a = i / 112, r = i - a * 112;
            uint32_t d = smb + (QK_OFF + a * SL) * 4 + r * 16;
            CP_ASYNC16(d,                t0 + i * 4);
            CP_ASYNC16(d + TSL * 4,      t1 + i * 4);
            CP_ASYNC16(d + 2 * TSL * 4,  t2 + i * 4);
            CP_ASYNC16(d + 3 * TSL * 4,  t3 + i * 4);
        }
        CP_COMMIT();
    }

    // ---- groups 1,2: v chunks 0,1 (in flight during logits) ----
    issue_chunk(vH, vW, smb, n, 0, Cv, bstr, tid);
    if (nch > 1) issue_chunk(vH, vW, smb, n, 1, Cv, bstr, tid);

    // ---- wait q/k only ----
    if (nch > 1) CP_WAIT2(); else CP_WAIT1();
    __syncthreads();

    // ---- logits: 686 dots ----
    for (int t = tid; t < 686; t += NTHR) {
        const int pass = t >= 343;
        const int tt = t - pass * 343;
        const int hh = tt / 49, rem = tt % 49, ww = rem / 7, j = rem % 7;
        const int a   = pass ? hh : ww;
        const int row = pass ? ww : hh;
        const float* qp = sm + QK_OFF + pass * 2 * TSL + a * SL + row * 64;
        const float* kp = sm + QK_OFF + pass * 2 * TSL + TSL + a * SL + j;
        float s = 0.f;
        #pragma unroll
        for (int cc = 0; cc < 64; cc += 4) {
            float4 x = *(const float4*)(qp + cc);
            s += x.x * kp[cc * 7]       + x.y * kp[(cc + 1) * 7]
               + x.z * kp[(cc + 2) * 7] + x.w * kp[(cc + 3) * 7];
        }
        if (pass == 0 && hh == j) s = NEGV;
        sm[LG_OFF + (hh * 7 + ww) * 14 + pass * 7 + j] = s;
    }
    __syncthreads();

    // ---- softmax over 14 ----
    if (tid < 49) {
        const float* row = sm + LG_OFF + tid * 14;
        float m = row[0];
        #pragma unroll
        for (int s = 1; s < 14; s++) m = fmaxf(m, row[s]);
        float e[14];
        float sum = 0.f;
        #pragma unroll
        for (int s = 0; s < 14; s++) { e[s] = __expf(row[s] - m); sum += e[s]; }
        const float inv = 1.f / sum;
        #pragma unroll
        for (int s = 0; s < 7; s++) {
            sm[PH_OFF + tid * 8 + s] = e[s]     * inv;
            sm[PW_OFF + tid * 8 + s] = e[s + 7] * inv;
        }
        sm[PH_OFF + tid * 8 + 7] = 0.f;
        sm[PW_OFF + tid * 8 + 7] = 0.f;
    }
    // (loop-top sync publishes PH/PW and retires qk before bounce reuse)

    // ---- chunk loop ----
    for (int ch = 0; ch < nch; ch++) {
        if (ch == nch - 1) CP_WAIT0(); else CP_WAIT1();
        __syncthreads();

        const int cmax = (Cv - ch * 64 >= 64) ? 64 : Cv - ch * 64;
        const int slot = (ch & 1) * 2;
        float acc[7];

        if (c < cmax) {
            const float* vhp = sm + VB_OFF + (slot + 0) * VSLOT + c * 7;
            const float* vwp = sm + VB_OFF + (slot + 1) * VSLOT + h * 448 + c * 7;
            const float* pHs = sm + PH_OFF;
            const float* pWs = sm + PW_OFF;

            float u0 = vwp[0], u1 = vwp[1], u2 = vwp[2], u3 = vwp[3],
                  u4 = vwp[4], u5 = vwp[5], u6 = vwp[6];

            #pragma unroll
            for (int w = 0; w < 7; w++) {
                const float* vp = vhp + w * 448;
                float v0 = vp[0], v1 = vp[1], v2 = vp[2], v3 = vp[3],
                      v4 = vp[4], v5 = vp[5], v6 = vp[6];
                const float4 p0 = *(const float4*)(pHs + (h * 7 + w) * 8);
                const float4 p1 = *(const float4*)(pHs + (h * 7 + w) * 8 + 4);
                acc[w] = p0.x * v0 + p0.y * v1 + p0.z * v2 + p0.w * v3
                       + p1.x * v4 + p1.y * v5 + p1.z * v6;
            }
            #pragma unroll
            for (int w = 0; w < 7; w++) {
                const float4 p0 = *(const float4*)(pWs + (h * 7 + w) * 8);
                const float4 p1 = *(const float4*)(pWs + (h * 7 + w) * 8 + 4);
                acc[w] += p0.x * u0 + p0.y * u1 + p0.z * u2 + p0.w * u3
                        + p1.x * u4 + p1.y * u5 + p1.z * u6;
            }
        }
        __syncthreads();          // v slot + bounce reads (prev STG) retired

        if (ch + 2 < nch) issue_chunk(vH, vW, smb, n, ch + 2, Cv, bstr, tid);

        if (c < cmax) {
            #pragma unroll
            for (int w = 0; w < 7; w++)
                sm[BN_OFF + (h * 7 + w) * CPADB + c] = acc[w];
        }
        __syncthreads();

        {
            float* ob = out + ((size_t)n * Cv + ch * 64) * 49;
            const int total = cmax * 49;
            for (int i = tid; i < total; i += NTHR) {
                int cc = i / 49;
                int hw = i - cc * 49;
                ob[i] = sm[BN_OFF + hw * CPADB + cc];
            }
        }
    }
}

extern "C" void kernel_launch(void* const* d_in, const int* in_sizes, int n_in,
                              void* d_out, int out_size)
{
    const float* qH = (const float*)d_in[0];
    const float* kH = (const float*)d_in[1];
    const float* vH = (const float*)d_in[2];
    const float* qW = (const float*)d_in[3];
    const float* kW = (const float*)d_in[4];
    const float* vW = (const float*)d_in[5];

    int N  = in_sizes[0] / (49 * 64);
    int Cv = in_sizes[2] / (N * 49);

    static bool attr_done = false;
    if (!attr_done) {
        cudaFuncSetAttribute(axattn_one,
                             cudaFuncAttributeMaxDynamicSharedMemorySize,
                             SMEM_BYTES);
        attr_done = true;
    }

    axattn_one<<<N, NTHR, SMEM_BYTES>>>(qH, kH, vH, qW, kW, vW,
                                        (float*)d_out, Cv);
}

// round 13
// speedup vs baseline: 1.1132x; 1.1132x over previous
#include <cuda_runtime.h>
#include <cstdint>
#include <cstddef>

// Axial attention on a 7x7 grid (N=512, Cq=64, Cv=512).
// out[n,c,h,w] = sum_j p[n,h,w,j]   * vH[(n*7+w), c, j]
//             + sum_y p[n,h,w,7+y] * vW[(n*7+h), c, y]
// p = softmax over 14 of [eH (diag-masked, transposed), eW].
//
// Two kernels linked by Programmatic Dependent Launch: ax_pv launches while
// ax_logits is still running, issues its v cp.asyncs, then griddepcontrol.wait
// gates the g_lg reads. Compute bodies identical to the best-known (R9) pair.

#define NEGV (-1e20f)
#define MAXN 1024

__device__ float g_lg[(size_t)MAXN * 49 * 14];

static __device__ __forceinline__ uint32_t s2u(const void* p) {
    return (uint32_t)__cvta_generic_to_shared(p);
}
#define CP_ASYNC16(dst_u32, src_ptr) \
    asm volatile("cp.async.cg.shared.global [%0], [%1], 16;" \
                 :: "r"(dst_u32), "l"(src_ptr))
#define CP_COMMIT()  asm volatile("cp.async.commit_group;")
#define CP_WAIT0()   asm volatile("cp.async.wait_group 0;")

// ---------------------------------------------------------------------------
// Kernel A: raw logits. Block = (n, pass), 384 threads. pass 0 = H, 1 = W.
// ---------------------------------------------------------------------------
#define SL 452
#define KOFF (7 * SL)

__global__ __launch_bounds__(384) void ax_logits(
    const float* __restrict__ qH, const float* __restrict__ kH,
    const float* __restrict__ qW, const float* __restrict__ kW)
{
    __shared__ float sm[2 * 7 * SL];

    const int n    = blockIdx.x;
    const int pass = blockIdx.y;
    const int tid  = threadIdx.x;

    const float4* q4 = (const float4*)((pass ? qW : qH) + (size_t)n * 3136);
    const float4* k4 = (const float4*)((pass ? kW : kH) + (size_t)n * 3136);
    float4* qs4 = (float4*)sm;
    float4* ks4 = (float4*)(sm + KOFF);

    for (int i = tid; i < 784; i += 384) {
        int a = i / 112, r = i - a * 112;
        qs4[a * 113 + r] = q4[i];
        ks4[a * 113 + r] = k4[i];
    }
    __syncthreads();

    if (tid < 343) {
        const int h = tid / 49, rem = tid % 49, w = rem / 7, j = rem % 7;
        const int a   = pass ? h : w;
        const int row = pass ? w : h;
        const float* qp = sm + a * SL + row * 64;
        const float* kp = sm + KOFF + a * SL + j;
        float s = 0.f;
        #pragma unroll
        for (int c = 0; c < 64; c += 4) {
            float4 x = *(const float4*)(qp + c);
            s += x.x * kp[c * 7]       + x.y * kp[(c + 1) * 7]
               + x.z * kp[(c + 2) * 7] + x.w * kp[(c + 3) * 7];
        }
        if (pass == 0 && h == j) s = NEGV;
        g_lg[(size_t)n * 686 + (size_t)(h * 7 + w) * 14 + pass * 7 + j] = s;
    }

    // Signal dependents: all prior writes (g_lg) become visible to the
    // consumer's griddepcontrol.wait once every CTA has issued this.
    asm volatile("griddepcontrol.launch_dependents;" ::: "memory");
}

// ---------------------------------------------------------------------------
// Kernel B: softmax + PV (R9 body). Block = (c-chunk of 128, n), 256 thr.
// PDL: v cp.asyncs issue BEFORE griddepcontrol.wait; softmax threads read
// g_lg directly from L2 after the wait (no staging pass, one less barrier).
// ---------------------------------------------------------------------------
#define CHUNK  128
#define PH_OFF 0
#define PW_OFF 392
#define VH_OFF 784
#define VW_OFF 7056
#define BN_OFF 784                   // bounce aliases vh (tail spills into vw)
#define CPADB  129
#define SMEMB_FLOATS 13328           // 53312 B -> 4 blocks/SM
#define SMEMB_BYTES (SMEMB_FLOATS * 4)

template<int HBASE, int NH>
static __device__ __forceinline__ void pv_compute2(
    const float* __restrict__ sm, int c1, int c2,
    float acc1[NH][7], float acc2[NH][7])
{
    const float* pHs = sm + PH_OFF;
    const float* pWs = sm + PW_OFF;

    #pragma unroll
    for (int w = 0; w < 7; w++) {
        const float* va = sm + VH_OFF + w * 896 + c1 * 7;
        const float* vb = sm + VH_OFF + w * 896 + c2 * 7;
        float a0 = va[0], a1 = va[1], a2 = va[2], a3 = va[3],
              a4 = va[4], a5 = va[5], a6 = va[6];
        float b0 = vb[0], b1 = vb[1], b2 = vb[2], b3 = vb[3],
              b4 = vb[4], b5 = vb[5], b6 = vb[6];
        #pragma unroll
        for (int hh = 0; hh < NH; hh++) {
            const int h = HBASE + hh;
            const float4 p0 = *(const float4*)(pHs + (h * 7 + w) * 8);
            const float4 p1 = *(const float4*)(pHs + (h * 7 + w) * 8 + 4);
            acc1[hh][w] = p0.x * a0 + p0.y * a1 + p0.z * a2 + p0.w * a3
                        + p1.x * a4 + p1.y * a5 + p1.z * a6;
            acc2[hh][w] = p0.x * b0 + p0.y * b1 + p0.z * b2 + p0.w * b3
                        + p1.x * b4 + p1.y * b5 + p1.z * b6;
        }
    }
    #pragma unroll
    for (int hh = 0; hh < NH; hh++) {
        const int h = HBASE + hh;
        const float* va = sm + VW_OFF + h * 896 + c1 * 7;
        const float* vb = sm + VW_OFF + h * 896 + c2 * 7;
        float a0 = va[0], a1 = va[1], a2 = va[2], a3 = va[3],
              a4 = va[4], a5 = va[5], a6 = va[6];
        float b0 = vb[0], b1 = vb[1], b2 = vb[2], b3 = vb[3],
              b4 = vb[4], b5 = vb[5], b6 = vb[6];
        #pragma unroll
        for (int w = 0; w < 7; w++) {
            const float4 p0 = *(const float4*)(pWs + (h * 7 + w) * 8);
            const float4 p1 = *(const float4*)(pWs + (h * 7 + w) * 8 + 4);
            acc1[hh][w] += p0.x * a0 + p0.y * a1 + p0.z * a2 + p0.w * a3
                         + p1.x * a4 + p1.y * a5 + p1.z * a6;
            acc2[hh][w] += p0.x * b0 + p0.y * b1 + p0.z * b2 + p0.w * b3
                         + p1.x * b4 + p1.y * b5 + p1.z * b6;
        }
    }
}

template<int HBASE, int NH>
static __device__ __forceinline__ void pv_store2(
    float* __restrict__ bnc, int c1, int c2,
    const float acc1[NH][7], const float acc2[NH][7])
{
    #pragma unroll
    for (int hh = 0; hh < NH; hh++)
        #pragma unroll
        for (int w = 0; w < 7; w++) {
            bnc[((HBASE + hh) * 7 + w) * CPADB + c1] = acc1[hh][w];
            bnc[((HBASE + hh) * 7 + w) * CPADB + c2] = acc2[hh][w];
        }
}

__global__ __launch_bounds__(256, 4) void ax_pv(
    const float* __restrict__ vH, const float* __restrict__ vW,
    float* __restrict__ out, int Cv)
{
    extern __shared__ float sm[];
    float* pHs = sm + PH_OFF;
    float* pWs = sm + PW_OFF;

    const int n   = blockIdx.y;
    const int c0  = blockIdx.x * CHUNK;
    const int tid = threadIdx.x;
    const int c1  = tid & 63;
    const int c2  = c1 + 64;
    const int q   = tid >> 6;

    const size_t bstr = (size_t)Cv * 7;
    const uint32_t smb = s2u(sm);

    // ---- issue ALL v cp.asyncs (independent of producer kernel) ----
    {
        const float* bh = vH + (size_t)n * 7 * bstr + (size_t)c0 * 7;
        const float* bw = vW + (size_t)n * 7 * bstr + (size_t)c0 * 7;
        for (int i = tid; i < 1568; i += 256) {
            int w = i / 224, r = i - w * 224;
            CP_ASYNC16(smb + (VH_OFF + w * 896 + r * 4) * 4,
                       bh + w * bstr + r * 4);
            CP_ASYNC16(smb + (VW_OFF + w * 896 + r * 4) * 4,
                       bw + w * bstr + r * 4);
        }
        CP_COMMIT();
    }

    // ---- gate on producer kernel's g_lg writes ----
    asm volatile("griddepcontrol.wait;" ::: "memory");

    // ---- softmax over 14 (direct L2 reads of just-written logits) ----
    if (tid < 49) {
        const float* row = g_lg + (size_t)n * 686 + tid * 14;
        float l[14];
        #pragma unroll
        for (int s = 0; s < 14; s++) l[s] = row[s];
        float m = l[0];
        #pragma unroll
        for (int s = 1; s < 14; s++) m = fmaxf(m, l[s]);
        float e[14];
        float sum = 0.f;
        #pragma unroll
        for (int s = 0; s < 14; s++) { e[s] = __expf(l[s] - m); sum += e[s]; }
        const float inv = 1.f / sum;
        #pragma unroll
        for (int s = 0; s < 7; s++) {
            pHs[tid * 8 + s] = e[s]     * inv;
            pWs[tid * 8 + s] = e[s + 7] * inv;
        }
        pHs[tid * 8 + 7] = 0.f;
        pWs[tid * 8 + 7] = 0.f;
    }

    CP_WAIT0();
    __syncthreads();

    float* bnc = sm + BN_OFF;

    if (q == 0) {
        float acc1[2][7], acc2[2][7];
        pv_compute2<0, 2>(sm, c1, c2, acc1, acc2);
        __syncthreads();
        pv_store2<0, 2>(bnc, c1, c2, acc1, acc2);
    } else if (q == 1) {
        float acc1[2][7], acc2[2][7];
        pv_compute2<2, 2>(sm, c1, c2, acc1, acc2);
        __syncthreads();
        pv_store2<2, 2>(bnc, c1, c2, acc1, acc2);
    } else if (q == 2) {
        float acc1[2][7], acc2[2][7];
        pv_compute2<4, 2>(sm, c1, c2, acc1, acc2);
        __syncthreads();
        pv_store2<4, 2>(bnc, c1, c2, acc1, acc2);
    } else {
        float acc1[1][7], acc2[1][7];
        pv_compute2<6, 1>(sm, c1, c2, acc1, acc2);
        __syncthreads();
        pv_store2<6, 1>(bnc, c1, c2, acc1, acc2);
    }
    __syncthreads();

    {
        float* ob = out + ((size_t)n * Cv + c0) * 49;
        int cc = tid / 49;
        int hw = tid - cc * 49;
        for (int i = tid; i < CHUNK * 49; i += 256) {
            ob[i] = bnc[hw * CPADB + cc];
            hw += 11; cc += 5;               // 256 = 5*49 + 11
            if (hw >= 49) { hw -= 49; cc += 1; }
        }
    }
}

extern "C" void kernel_launch(void* const* d_in, const int* in_sizes, int n_in,
                              void* d_out, int out_size)
{
    const float* qH = (const float*)d_in[0];
    const float* kH = (const float*)d_in[1];
    const float* vH = (const float*)d_in[2];
    const float* qW = (const float*)d_in[3];
    const float* kW = (const float*)d_in[4];
    const float* vW = (const float*)d_in[5];

    int N  = in_sizes[0] / (49 * 64);
    int Cv = in_sizes[2] / (N * 49);

    static bool attr_done = false;
    if (!attr_done) {
        cudaFuncSetAttribute(ax_pv,
                             cudaFuncAttributeMaxDynamicSharedMemorySize,
                             SMEMB_BYTES);
        attr_done = true;
    }

    // Kernel A: normal launch.
    dim3 ga(N, 2);
    ax_logits<<<ga, 384>>>(qH, kH, qW, kW);

    // Kernel B: programmatic dependent launch (overlaps A's tail).
    {
        cudaLaunchConfig_t cfg = {};
        cfg.gridDim  = dim3((unsigned)((Cv + CHUNK - 1) / CHUNK), (unsigned)N);
        cfg.blockDim = dim3(256);
        cfg.dynamicSmemBytes = SMEMB_BYTES;
        cfg.stream = 0;
        cudaLaunchAttribute attr[1];
        attr[0].id = cudaLaunchAttributeProgrammaticStreamSerialization;
        attr[0].val.programmaticStreamSerializationAllowed = 1;
        cfg.attrs = attr;
        cfg.numAttrs = 1;
        cudaLaunchKernelEx(&cfg, ax_pv, vH, vW, (float*)d_out, Cv);
    }
}

// round 14
// speedup vs baseline: 1.1907x; 1.0697x over previous
#include <cuda_runtime.h>
#include <cstdint>
#include <cstddef>

// Axial attention on a 7x7 grid (N=512, Cq=64, Cv=512).
// out[n,c,h,w] = sum_j p[n,h,w,j]   * vH[(n*7+w), c, j]
//             + sum_y p[n,h,w,7+y] * vW[(n*7+h), c, y]
// p = softmax over 14 of [eH (diag-masked, transposed), eW].
//
// Producer/consumer pipelined via PDL + per-n flags:
//   A (1 block per n) computes logits, then red.release's g_flag[n].
//   B (PDL-launched, overlapping A) spins on g_flag[n] only -> per-n
//   dependency instead of grid-global, so A hides under B's v streaming.

#define NEGV (-1e20f)
#define MAXN 1024

__device__ float    g_lg[(size_t)MAXN * 49 * 14];
__device__ unsigned g_flag[MAXN];

static __device__ __forceinline__ uint32_t s2u(const void* p) {
    return (uint32_t)__cvta_generic_to_shared(p);
}
#define CP_ASYNC16(dst_u32, src_ptr) \
    asm volatile("cp.async.cg.shared.global [%0], [%1], 16;" \
                 :: "r"(dst_u32), "l"(src_ptr))
#define CP_COMMIT()  asm volatile("cp.async.commit_group;")
#define CP_WAIT0()   asm volatile("cp.async.wait_group 0;")

// ---------------------------------------------------------------------------
// Kernel A: logits for BOTH passes, one block per n, 384 threads.
// launch_dependents at entry -> B's grid launches almost immediately.
// smem: [qH][kH][qW][kW], each 7*SL floats (SL==4 mod 32 bank spread).
// ---------------------------------------------------------------------------
#define SL  452
#define TSL (7 * SL)
#define SMEMA_BYTES (4 * TSL * 4)     // 50624 B

__global__ __launch_bounds__(384) void ax_logits(
    const float* __restrict__ qH, const float* __restrict__ kH,
    const float* __restrict__ qW, const float* __restrict__ kW)
{
    extern __shared__ float sm[];

    asm volatile("griddepcontrol.launch_dependents;" ::: "memory");

    const int n   = blockIdx.x;
    const int tid = threadIdx.x;

    {
        const float4* t0 = (const float4*)(qH + (size_t)n * 3136);
        const float4* t1 = (const float4*)(kH + (size_t)n * 3136);
        const float4* t2 = (const float4*)(qW + (size_t)n * 3136);
        const float4* t3 = (const float4*)(kW + (size_t)n * 3136);
        for (int i = tid; i < 784; i += 384) {
            int a = i / 112, r = i - a * 112;
            ((float4*)(sm))[a * 113 + r]           = t0[i];
            ((float4*)(sm + TSL))[a * 113 + r]     = t1[i];
            ((float4*)(sm + 2 * TSL))[a * 113 + r] = t2[i];
            ((float4*)(sm + 3 * TSL))[a * 113 + r] = t3[i];
        }
    }
    __syncthreads();

    for (int t = tid; t < 686; t += 384) {
        const int pass = t >= 343;
        const int tt = t - pass * 343;
        const int h = tt / 49, rem = tt % 49, w = rem / 7, j = rem % 7;
        const int a   = pass ? h : w;
        const int row = pass ? w : h;
        const float* qp = sm + (pass ? 2 * TSL : 0) + a * SL + row * 64;
        const float* kp = sm + (pass ? 3 * TSL : TSL) + a * SL + j;
        float s = 0.f;
        #pragma unroll
        for (int c = 0; c < 64; c += 4) {
            float4 x = *(const float4*)(qp + c);
            s += x.x * kp[c * 7]       + x.y * kp[(c + 1) * 7]
               + x.z * kp[(c + 2) * 7] + x.w * kp[(c + 3) * 7];
        }
        if (pass == 0 && h == j) s = NEGV;
        g_lg[(size_t)n * 686 + (size_t)(h * 7 + w) * 14 + pass * 7 + j] = s;
    }
    __syncthreads();

    if (tid == 0) {
        __threadfence();
        asm volatile("red.release.gpu.global.add.u32 [%0], 1;"
                     :: "l"(&g_flag[n]) : "memory");
    }
}

// ---------------------------------------------------------------------------
// Kernel B: softmax + PV (R13 body). Block = (c-chunk of 128, n), 256 thr.
// Spins on g_flag[n] (per-n dependency) instead of griddepcontrol.wait.
// ---------------------------------------------------------------------------
#define CHUNK  128
#define PH_OFF 0
#define PW_OFF 392
#define VH_OFF 784
#define VW_OFF 7056
#define BN_OFF 784
#define CPADB  129
#define SMEMB_FLOATS 13328
#define SMEMB_BYTES (SMEMB_FLOATS * 4)

template<int HBASE, int NH>
static __device__ __forceinline__ void pv_compute2(
    const float* __restrict__ sm, int c1, int c2,
    float acc1[NH][7], float acc2[NH][7])
{
    const float* pHs = sm + PH_OFF;
    const float* pWs = sm + PW_OFF;

    #pragma unroll
    for (int w = 0; w < 7; w++) {
        const float* va = sm + VH_OFF + w * 896 + c1 * 7;
        const float* vb = sm + VH_OFF + w * 896 + c2 * 7;
        float a0 = va[0], a1 = va[1], a2 = va[2], a3 = va[3],
              a4 = va[4], a5 = va[5], a6 = va[6];
        float b0 = vb[0], b1 = vb[1], b2 = vb[2], b3 = vb[3],
              b4 = vb[4], b5 = vb[5], b6 = vb[6];
        #pragma unroll
        for (int hh = 0; hh < NH; hh++) {
            const int h = HBASE + hh;
            const float4 p0 = *(const float4*)(pHs + (h * 7 + w) * 8);
            const float4 p1 = *(const float4*)(pHs + (h * 7 + w) * 8 + 4);
            acc1[hh][w] = p0.x * a0 + p0.y * a1 + p0.z * a2 + p0.w * a3
                        + p1.x * a4 + p1.y * a5 + p1.z * a6;
            acc2[hh][w] = p0.x * b0 + p0.y * b1 + p0.z * b2 + p0.w * b3
                        + p1.x * b4 + p1.y * b5 + p1.z * b6;
        }
    }
    #pragma unroll
    for (int hh = 0; hh < NH; hh++) {
        const int h = HBASE + hh;
        const float* va = sm + VW_OFF + h * 896 + c1 * 7;
        const float* vb = sm + VW_OFF + h * 896 + c2 * 7;
        float a0 = va[0], a1 = va[1], a2 = va[2], a3 = va[3],
              a4 = va[4], a5 = va[5], a6 = va[6];
        float b0 = vb[0], b1 = vb[1], b2 = vb[2], b3 = vb[3],
              b4 = vb[4], b5 = vb[5], b6 = vb[6];
        #pragma unroll
        for (int w = 0; w < 7; w++) {
            const float4 p0 = *(const float4*)(pWs + (h * 7 + w) * 8);
            const float4 p1 = *(const float4*)(pWs + (h * 7 + w) * 8 + 4);
            acc1[hh][w] += p0.x * a0 + p0.y * a1 + p0.z * a2 + p0.w * a3
                         + p1.x * a4 + p1.y * a5 + p1.z * a6;
            acc2[hh][w] += p0.x * b0 + p0.y * b1 + p0.z * b2 + p0.w * b3
                         + p1.x * b4 + p1.y * b5 + p1.z * b6;
        }
    }
}

template<int HBASE, int NH>
static __device__ __forceinline__ void pv_store2(
    float* __restrict__ bnc, int c1, int c2,
    const float acc1[NH][7], const float acc2[NH][7])
{
    #pragma unroll
    for (int hh = 0; hh < NH; hh++)
        #pragma unroll
        for (int w = 0; w < 7; w++) {
            bnc[((HBASE + hh) * 7 + w) * CPADB + c1] = acc1[hh][w];
            bnc[((HBASE + hh) * 7 + w) * CPADB + c2] = acc2[hh][w];
        }
}

__global__ __launch_bounds__(256, 4) void ax_pv(
    const float* __restrict__ vH, const float* __restrict__ vW,
    float* __restrict__ out, int Cv)
{
    extern __shared__ float sm[];
    float* pHs = sm + PH_OFF;
    float* pWs = sm + PW_OFF;

    const int n   = blockIdx.y;
    const int c0  = blockIdx.x * CHUNK;
    const int tid = threadIdx.x;
    const int c1  = tid & 63;
    const int c2  = c1 + 64;
    const int q   = tid >> 6;

    const size_t bstr = (size_t)Cv * 7;
    const uint32_t smb = s2u(sm);

    // ---- issue ALL v cp.asyncs (independent of producer) ----
    {
        const float* bh = vH + (size_t)n * 7 * bstr + (size_t)c0 * 7;
        const float* bw = vW + (size_t)n * 7 * bstr + (size_t)c0 * 7;
        for (int i = tid; i < 1568; i += 256) {
            int w = i / 224, r = i - w * 224;
            CP_ASYNC16(smb + (VH_OFF + w * 896 + r * 4) * 4,
                       bh + w * bstr + r * 4);
            CP_ASYNC16(smb + (VW_OFF + w * 896 + r * 4) * 4,
                       bw + w * bstr + r * 4);
        }
        CP_COMMIT();
    }

    // ---- per-n dependency: spin until producer block n has released ----
    if (tid == 0) {
        unsigned v;
        while (true) {
            asm volatile("ld.acquire.gpu.global.u32 %0, [%1];"
                         : "=r"(v) : "l"(&g_flag[n]) : "memory");
            if (v) break;
            __nanosleep(64);
        }
    }
    __syncthreads();

    // ---- softmax over 14 (direct L2 reads of just-written logits) ----
    if (tid < 49) {
        const float* row = g_lg + (size_t)n * 686 + tid * 14;
        float l[14];
        #pragma unroll
        for (int s = 0; s < 14; s++) l[s] = row[s];
        float m = l[0];
        #pragma unroll
        for (int s = 1; s < 14; s++) m = fmaxf(m, l[s]);
        float e[14];
        float sum = 0.f;
        #pragma unroll
        for (int s = 0; s < 14; s++) { e[s] = __expf(l[s] - m); sum += e[s]; }
        const float inv = 1.f / sum;
        #pragma unroll
        for (int s = 0; s < 7; s++) {
            pHs[tid * 8 + s] = e[s]     * inv;
            pWs[tid * 8 + s] = e[s + 7] * inv;
        }
        pHs[tid * 8 + 7] = 0.f;
        pWs[tid * 8 + 7] = 0.f;
    }

    CP_WAIT0();
    __syncthreads();

    float* bnc = sm + BN_OFF;

    if (q == 0) {
        float acc1[2][7], acc2[2][7];
        pv_compute2<0, 2>(sm, c1, c2, acc1, acc2);
        __syncthreads();
        pv_store2<0, 2>(bnc, c1, c2, acc1, acc2);
    } else if (q == 1) {
        float acc1[2][7], acc2[2][7];
        pv_compute2<2, 2>(sm, c1, c2, acc1, acc2);
        __syncthreads();
        pv_store2<2, 2>(bnc, c1, c2, acc1, acc2);
    } else if (q == 2) {
        float acc1[2][7], acc2[2][7];
        pv_compute2<4, 2>(sm, c1, c2, acc1, acc2);
        __syncthreads();
        pv_store2<4, 2>(bnc, c1, c2, acc1, acc2);
    } else {
        float acc1[1][7], acc2[1][7];
        pv_compute2<6, 1>(sm, c1, c2, acc1, acc2);
        __syncthreads();
        pv_store2<6, 1>(bnc, c1, c2, acc1, acc2);
    }
    __syncthreads();

    {
        float* ob = out + ((size_t)n * Cv + c0) * 49;
        int cc = tid / 49;
        int hw = tid - cc * 49;
        for (int i = tid; i < CHUNK * 49; i += 256) {
            ob[i] = bnc[hw * CPADB + cc];
            hw += 11; cc += 5;               // 256 = 5*49 + 11
            if (hw >= 49) { hw -= 49; cc += 1; }
        }
    }
}

extern "C" void kernel_launch(void* const* d_in, const int* in_sizes, int n_in,
                              void* d_out, int out_size)
{
    const float* qH = (const float*)d_in[0];
    const float* kH = (const float*)d_in[1];
    const float* vH = (const float*)d_in[2];
    const float* qW = (const float*)d_in[3];
    const float* kW = (const float*)d_in[4];
    const float* vW = (const float*)d_in[5];

    int N  = in_sizes[0] / (49 * 64);
    int Cv = in_sizes[2] / (N * 49);

    static void* flag_addr = nullptr;
    if (!flag_addr) {
        cudaFuncSetAttribute(ax_logits,
                             cudaFuncAttributeMaxDynamicSharedMemorySize,
                             SMEMA_BYTES);
        cudaFuncSetAttribute(ax_pv,
                             cudaFuncAttributeMaxDynamicSharedMemorySize,
                             SMEMB_BYTES);
        cudaGetSymbolAddress(&flag_addr, g_flag);
    }

    // Deterministic flag reset (graph-legal memset node).
    cudaMemsetAsync(flag_addr, 0, (size_t)N * sizeof(unsigned), 0);

    // Kernel A: normal launch, one block per n.
    ax_logits<<<N, 384, SMEMA_BYTES>>>(qH, kH, qW, kW);

    // Kernel B: programmatic dependent launch; correctness gated by flags.
    {
        cudaLaunchConfig_t cfg = {};
        cfg.gridDim  = dim3((unsigned)((Cv + CHUNK - 1) / CHUNK), (unsigned)N);
        cfg.blockDim = dim3(256);
        cfg.dynamicSmemBytes = SMEMB_BYTES;
        cfg.stream = 0;
        cudaLaunchAttribute attr[1];
        attr[0].id = cudaLaunchAttributeProgrammaticStreamSerialization;
        attr[0].val.programmaticStreamSerializationAllowed = 1;
        cfg.attrs = attr;
        cfg.numAttrs = 1;
        cudaLaunchKernelEx(&cfg, ax_pv, vH, vW, (float*)d_out, Cv);
    }
}